// round 5
// baseline (speedup 1.0000x reference)
#include <cuda_runtime.h>
#include <cstdint>

// P: [N=12, T=4096, D=2048] fp32; subgroup_indices: [2,6] (int32 or int64);
// out: [1, T, 2*D] fp32 ; out[t, s*D+d] = max_{g<6} P[idx[s*6+g], t, d]
//
// Pure HBM streaming: 403 MB read + 67 MB write, zero reuse. R3 showed we sit
// at ~84% DRAM. This round: persistent single-wave grid (148 SMs x 8 CTAs),
// grid-stride loop unrolled x2 -> 12 independent LDG.128 in flight per thread,
// no wave transitions, no CTA launch/retire churn. Base pointers hoisted.

#define T_FRAMES   4096
#define D_DIM      2048
#define D4         (D_DIM / 4)          // 512 float4 per (n,t) row
#define OUT_F4     (T_FRAMES * 2 * D4)  // 4,194,304 output float4
#define FRAME_F4   (2 * D4)             // 1024 float4 per output frame
#define TD4        ((long long)T_FRAMES * D4)

#define NUM_SMS    148
#define CTAS_PER_SM 8
#define GRID_CTAS  (NUM_SMS * CTAS_PER_SM)   // 1184
#define THREADS    256

__device__ __forceinline__ float4 f4max(float4 a, float4 b) {
    a.x = fmaxf(a.x, b.x);
    a.y = fmaxf(a.y, b.y);
    a.z = fmaxf(a.z, b.z);
    a.w = fmaxf(a.w, b.w);
    return a;
}

__global__ __launch_bounds__(THREADS) void subgroup_maxpool_kernel(
    const float4* __restrict__ P4,
    const int*    __restrict__ idx_words,
    float4*       __restrict__ out4)
{
    // Detect index dtype once: int64 arange -> words 0,0,1,0,... (word[1]==0)
    //                          int32 arange -> words 0,1,2,...   (word[1]==1)
    const bool is64 = (idx_words[1] == 0);

    // Hoist the 12 player base pointers (values are runtime data, layout fixed).
    const float4* base[12];
    #pragma unroll
    for (int j = 0; j < 12; ++j) {
        const int n = is64 ? idx_words[2 * j] : idx_words[j];
        base[j] = P4 + (long long)n * TD4;
    }

    const int stride = GRID_CTAS * THREADS;
    int i = blockIdx.x * THREADS + threadIdx.x;

    #pragma unroll 2
    for (; i < OUT_F4; i += stride) {
        const int t   = i >> 10;             // / FRAME_F4
        const int rem = i & (FRAME_F4 - 1);
        const int s   = rem >> 9;            // / D4
        const int d4  = rem & (D4 - 1);
        const long long col = (long long)t * D4 + d4;
        const int b = s * 6;

        float4 m = __ldcs(base[b + 0] + col);
        m = f4max(m, __ldcs(base[b + 1] + col));
        m = f4max(m, __ldcs(base[b + 2] + col));
        m = f4max(m, __ldcs(base[b + 3] + col));
        m = f4max(m, __ldcs(base[b + 4] + col));
        m = f4max(m, __ldcs(base[b + 5] + col));

        __stcs(&out4[i], m);
    }
}

extern "C" void kernel_launch(void* const* d_in, const int* in_sizes, int n_in,
                              void* d_out, int out_size)
{
    const float4* P4  = (const float4*)d_in[0];
    const int*    idx = (const int*)d_in[1];
    float4*       out = (float4*)d_out;

    subgroup_maxpool_kernel<<<GRID_CTAS, THREADS>>>(P4, idx, out);
}

// round 6
// speedup vs baseline: 1.0031x; 1.0031x over previous
#include <cuda_runtime.h>
#include <cstdint>

// P: [N=12, T=4096, D=2048] fp32; subgroup_indices: [2,6] (int32 or int64);
// out: [1, T, 2*D] fp32 ; out[t, s*D+d] = max_{g<6} P[idx[s*6+g], t, d]
//
// Pure HBM streaming: 403 MB read + 67 MB write, zero reuse. R3 showed we sit
// at ~84% DRAM. This round: persistent single-wave grid (148 SMs x 8 CTAs),
// grid-stride loop unrolled x2 -> 12 independent LDG.128 in flight per thread,
// no wave transitions, no CTA launch/retire churn. Base pointers hoisted.

#define T_FRAMES   4096
#define D_DIM      2048
#define D4         (D_DIM / 4)          // 512 float4 per (n,t) row
#define OUT_F4     (T_FRAMES * 2 * D4)  // 4,194,304 output float4
#define FRAME_F4   (2 * D4)             // 1024 float4 per output frame
#define TD4        ((long long)T_FRAMES * D4)

#define NUM_SMS    148
#define CTAS_PER_SM 8
#define GRID_CTAS  (NUM_SMS * CTAS_PER_SM)   // 1184
#define THREADS    256

__device__ __forceinline__ float4 f4max(float4 a, float4 b) {
    a.x = fmaxf(a.x, b.x);
    a.y = fmaxf(a.y, b.y);
    a.z = fmaxf(a.z, b.z);
    a.w = fmaxf(a.w, b.w);
    return a;
}

__global__ __launch_bounds__(THREADS) void subgroup_maxpool_kernel(
    const float4* __restrict__ P4,
    const int*    __restrict__ idx_words,
    float4*       __restrict__ out4)
{
    // Detect index dtype once: int64 arange -> words 0,0,1,0,... (word[1]==0)
    //                          int32 arange -> words 0,1,2,...   (word[1]==1)
    const bool is64 = (idx_words[1] == 0);

    // Hoist the 12 player base pointers (values are runtime data, layout fixed).
    const float4* base[12];
    #pragma unroll
    for (int j = 0; j < 12; ++j) {
        const int n = is64 ? idx_words[2 * j] : idx_words[j];
        base[j] = P4 + (long long)n * TD4;
    }

    const int stride = GRID_CTAS * THREADS;
    int i = blockIdx.x * THREADS + threadIdx.x;

    #pragma unroll 2
    for (; i < OUT_F4; i += stride) {
        const int t   = i >> 10;             // / FRAME_F4
        const int rem = i & (FRAME_F4 - 1);
        const int s   = rem >> 9;            // / D4
        const int d4  = rem & (D4 - 1);
        const long long col = (long long)t * D4 + d4;
        const int b = s * 6;

        float4 m = __ldcs(base[b + 0] + col);
        m = f4max(m, __ldcs(base[b + 1] + col));
        m = f4max(m, __ldcs(base[b + 2] + col));
        m = f4max(m, __ldcs(base[b + 3] + col));
        m = f4max(m, __ldcs(base[b + 4] + col));
        m = f4max(m, __ldcs(base[b + 5] + col));

        __stcs(&out4[i], m);
    }
}

extern "C" void kernel_launch(void* const* d_in, const int* in_sizes, int n_in,
                              void* d_out, int out_size)
{
    const float4* P4  = (const float4*)d_in[0];
    const int*    idx = (const int*)d_in[1];
    float4*       out = (float4*)d_out;

    subgroup_maxpool_kernel<<<GRID_CTAS, THREADS>>>(P4, idx, out);
}